// round 4
// baseline (speedup 1.0000x reference)
#include <cuda_runtime.h>
#include <cstddef>

// Truncated depth-3 path signature, B=512, L=512, C=8.
// out[b] = concat(S1(8), S2(64), S3(512)) = 584 floats per batch.
//
// Strategy: Chen's identity is associative over stream concatenation:
//   (A o B)_1 = A1+B1
//   (A o B)_2 = A2+B2+A1(x)B1
//   (A o B)_3 = A3+B3+A1(x)B2+A2(x)B1
// Split the 511 increments into 8 chunks per batch. One warp per
// (batch, chunk) computes its chunk signature fully in registers
// (no barriers in the hot loop; dx broadcast via 8 shfl + SEL trees).
// Then a 3-round in-block tree combine through shared memory, and a
// block-wide store of the 584 outputs.

#define FULLMASK 0xffffffffu
#define L_STREAM 512
#define CH 8
#define NCHUNK 8
#define CHUNK_STEPS 64          // chunks 0..6 have 64 increments, chunk 7 has 63
#define SIGLEN 584              // 8 + 64 + 512

typedef unsigned long long u64;

__device__ __forceinline__ u64 pk2(float lo, float hi) {
    u64 r;
    asm("mov.b64 %0, {%1, %2};" : "=l"(r) : "f"(lo), "f"(hi));
    return r;
}
__device__ __forceinline__ void unpk2(u64 v, float& lo, float& hi) {
    asm("mov.b64 {%0, %1}, %2;" : "=f"(lo), "=f"(hi) : "l"(v));
}
// Packed fp32x2 FMA (Blackwell sm_100+): two FFMAs per instruction.
__device__ __forceinline__ u64 ffma2(u64 a, u64 b, u64 c) {
    u64 d;
    asm("fma.rn.f32x2 %0, %1, %2, %3;" : "=l"(d) : "l"(a), "l"(b), "l"(c));
    return d;
}

// Warp-collective Chen combine: A <- A o B, both in shared memory.
// Lane t owns flat S2/S3 pairs p0=2t, p1=2t+1 (both share i = p0>>3).
__device__ __forceinline__ void chen_combine_warp(float* A, const float* B, int t) {
    const int p0 = 2 * t, p1 = p0 + 1;
    const int i = p0 >> 3, j0 = p0 & 7, j1 = j0 + 1;

    const float A1i  = A[i];
    const float B1j0 = B[j0];
    const float B1j1 = B[j1];
    const float A2p0 = A[8 + p0];
    const float A2p1 = A[8 + p1];

    float*       A3_0 = A + 72 + p0 * 8;
    float*       A3_1 = A + 72 + p1 * 8;
    const float* B3_0 = B + 72 + p0 * 8;
    const float* B3_1 = B + 72 + p1 * 8;
    const float* B2_0 = B + 8 + j0 * 8;
    const float* B2_1 = B + 8 + j1 * 8;

    #pragma unroll
    for (int k = 0; k < 8; k++) {
        float b1k = B[k];
        float v0 = A3_0[k] + B3_0[k];
        v0 = fmaf(A1i,  B2_0[k], v0);
        v0 = fmaf(A2p0, b1k,     v0);
        A3_0[k] = v0;
        float v1 = A3_1[k] + B3_1[k];
        v1 = fmaf(A1i,  B2_1[k], v1);
        v1 = fmaf(A2p1, b1k,     v1);
        A3_1[k] = v1;
    }
    A[8 + p0] = fmaf(A1i, B1j0, A2p0 + B[8 + p0]);
    A[8 + p1] = fmaf(A1i, B1j1, A2p1 + B[8 + p1]);
    __syncwarp();
    if (t < 8) A[t] += B[t];   // level-1 last (A1i already read by all lanes)
}

extern "C" __global__ void __launch_bounds__(256)
signature_kernel(const float* __restrict__ path, float* __restrict__ out) {
    __shared__ float sig[NCHUNK][SIGLEN];

    const int b = blockIdx.x;
    const int w = threadIdx.x >> 5;   // chunk id 0..7
    const int t = threadIdx.x & 31;   // lane

    const int p0 = 2 * t;
    const int p1 = p0 + 1;
    const int i  = p0 >> 3;           // i index shared by both owned pairs
    const int j0 = p0 & 7;            // even; j1 = j0+1 odd
    const int col = t & 7;            // this lane's channel for dx broadcast

    // loop-invariant select predicates for the SEL trees
    const bool i2 = (i & 4) != 0, i1 = (i & 2) != 0, i0 = (i & 1) != 0;
    const bool ja = (j0 & 4) != 0, jb = (j0 & 2) != 0;

    const float* base = path + ((size_t)b * L_STREAM + (size_t)w * CHUNK_STEPS) * CH;
    const int steps = (w < NCHUNK - 1) ? CHUNK_STEPS : (CHUNK_STEPS - 1); // 511 total

    // rolling per-lane channel value; S1 is recovered as end - start
    const float vstart = base[col];
    float vcur = vstart;

    float s1i = 0.f;                  // S1[i], the only S1 entry this lane needs
    float s2_0 = 0.f, s2_1 = 0.f;     // S2[p0], S2[p1]
    u64 s3[8];                        // S3[p0][0..7], S3[p1][0..7] packed as f32x2
    #pragma unroll
    for (int q = 0; q < 8; q++) s3[q] = 0ull;

    const float* rp = base + CH + col;   // element `col` of row (s+1)

    #pragma unroll 4
    for (int s = 0; s < steps; s++) {
        // per-lane increment of channel `col`, then warp-broadcast
        float v = rp[(size_t)s * CH];
        float dval = v - vcur;
        vcur = v;

        float d0 = __shfl_sync(FULLMASK, dval, 0);
        float d1 = __shfl_sync(FULLMASK, dval, 1);
        float d2 = __shfl_sync(FULLMASK, dval, 2);
        float d3 = __shfl_sync(FULLMASK, dval, 3);
        float d4 = __shfl_sync(FULLMASK, dval, 4);
        float d5 = __shfl_sync(FULLMASK, dval, 5);
        float d6 = __shfl_sync(FULLMASK, dval, 6);
        float d7 = __shfl_sync(FULLMASK, dval, 7);

        // di = d[i], dj0 = d[j0] (even), dj1 = d[j0+1] (odd): SEL trees on
        // loop-invariant predicates instead of 3 extra shuffles (ALU pipe,
        // not MIO).
        float di  = i2 ? (i1 ? (i0 ? d7 : d6) : (i0 ? d5 : d4))
                       : (i1 ? (i0 ? d3 : d2) : (i0 ? d1 : d0));
        float dj0 = ja ? (jb ? d6 : d4) : (jb ? d2 : d0);
        float dj1 = ja ? (jb ? d7 : d5) : (jb ? d3 : d1);

        u64 dxp0 = pk2(d0, d1);
        u64 dxp1 = pk2(d2, d3);
        u64 dxp2 = pk2(d4, d5);
        u64 dxp3 = pk2(d6, d7);

        // S3[p][k] += dx_k * ( dx_j*(dx_i/6 + S1_i/2) + S2_p )
        // S2[p]    += dx_j * ( dx_i/2 + S1_i )
        // (S1, S2 read as pre-step values)
        float g = fmaf(s1i, 0.5f, di * (1.0f / 6.0f));
        float h = fmaf(di, 0.5f, s1i);
        float a0 = fmaf(dj0, g, s2_0);
        float a1 = fmaf(dj1, g, s2_1);
        s2_0 = fmaf(dj0, h, s2_0);
        s2_1 = fmaf(dj1, h, s2_1);
        s1i += di;

        u64 a00 = pk2(a0, a0);
        u64 a11 = pk2(a1, a1);
        s3[0] = ffma2(dxp0, a00, s3[0]);
        s3[1] = ffma2(dxp1, a00, s3[1]);
        s3[2] = ffma2(dxp2, a00, s3[2]);
        s3[3] = ffma2(dxp3, a00, s3[3]);
        s3[4] = ffma2(dxp0, a11, s3[4]);
        s3[5] = ffma2(dxp1, a11, s3[5]);
        s3[6] = ffma2(dxp2, a11, s3[6]);
        s3[7] = ffma2(dxp3, a11, s3[7]);
    }

    // ---- publish chunk partial signature to shared ----
    if (t < 8) sig[w][t] = vcur - vstart;     // S1 = total increment of the chunk
    sig[w][8 + p0] = s2_0;
    sig[w][8 + p1] = s2_1;
    #pragma unroll
    for (int q = 0; q < 4; q++) {
        float lo, hi;
        unpk2(s3[q], lo, hi);
        sig[w][72 + p0 * 8 + 2 * q]     = lo;
        sig[w][72 + p0 * 8 + 2 * q + 1] = hi;
        unpk2(s3[4 + q], lo, hi);
        sig[w][72 + p1 * 8 + 2 * q]     = lo;
        sig[w][72 + p1 * 8 + 2 * q + 1] = hi;
    }
    __syncthreads();

    // ---- 3-round Chen tree combine (order-preserving) ----
    if (w < 4) chen_combine_warp(sig[2 * w], sig[2 * w + 1], t);   // (0,1)(2,3)(4,5)(6,7)
    __syncthreads();
    if (w < 2) chen_combine_warp(sig[4 * w], sig[4 * w + 2], t);   // (0,2)(4,6)
    __syncthreads();
    if (w == 0) chen_combine_warp(sig[0], sig[4], t);              // (0,4)
    __syncthreads();

    float* o = out + (size_t)b * SIGLEN;
    for (int idx = threadIdx.x; idx < SIGLEN; idx += 256) o[idx] = sig[0][idx];
}

extern "C" void kernel_launch(void* const* d_in, const int* in_sizes, int n_in,
                              void* d_out, int out_size) {
    const float* path = (const float*)d_in[0];
    float* out = (float*)d_out;
    const int batches = in_sizes[0] / (L_STREAM * CH);   // 512
    signature_kernel<<<batches, 256>>>(path, out);
}

// round 10
// speedup vs baseline: 1.3485x; 1.3485x over previous
#include <cuda_runtime.h>
#include <cstddef>

// Truncated depth-3 path signature, B=512, L=512, C=8.
// out[b] = concat(S1(8), S2(64), S3(512)) = 584 floats per batch.
//
// Chen-associative chunked scan: 8 chunks per batch, one warp per
// (batch, chunk). The per-step dx broadcast uses 2 uniform-address
// LDG.128 per row (1 sector each, L1 broadcast) instead of 8 SHFLs
// (R4 profile: L1tex 54% = MIO/shfl-latency bound); dx = row - prev
// is computed as packed f32x2 in registers.
// sig is __align__(16) (u64/STS.64 stores into it).

#define FULLMASK 0xffffffffu
#define L_STREAM 512
#define CH 8
#define NCHUNK 8
#define CHUNK_STEPS 64          // chunks 0..6 have 64 increments, chunk 7 has 63
#define SIGLEN 584              // 8 + 64 + 512

typedef unsigned long long u64;

#define NEG1X2 0xBF800000BF800000ull   // packed {-1.0f, -1.0f}

__device__ __forceinline__ u64 pk2(float lo, float hi) {
    u64 r;
    asm("mov.b64 %0, {%1, %2};" : "=l"(r) : "f"(lo), "f"(hi));
    return r;
}
__device__ __forceinline__ void unpk2(u64 v, float& lo, float& hi) {
    asm("mov.b64 {%0, %1}, %2;" : "=f"(lo), "=f"(hi) : "l"(v));
}
// Packed fp32x2 FMA (Blackwell sm_100+): two FFMAs per instruction.
__device__ __forceinline__ u64 ffma2(u64 a, u64 b, u64 c) {
    u64 d;
    asm("fma.rn.f32x2 %0, %1, %2, %3;" : "=l"(d) : "l"(a), "l"(b), "l"(c));
    return d;
}

// Warp-collective Chen combine: A <- A o B, both in shared memory.
// Lane t owns flat S2/S3 pairs p0=2t, p1=2t+1 (both share i = p0>>3).
__device__ __forceinline__ void chen_combine_warp(float* A, const float* B, int t) {
    const int p0 = 2 * t, p1 = p0 + 1;
    const int i = p0 >> 3, j0 = p0 & 7, j1 = j0 + 1;

    const float A1i  = A[i];
    const float B1j0 = B[j0];
    const float B1j1 = B[j1];
    const float A2p0 = A[8 + p0];
    const float A2p1 = A[8 + p1];

    float*       A3_0 = A + 72 + p0 * 8;
    float*       A3_1 = A + 72 + p1 * 8;
    const float* B3_0 = B + 72 + p0 * 8;
    const float* B3_1 = B + 72 + p1 * 8;
    const float* B2_0 = B + 8 + j0 * 8;
    const float* B2_1 = B + 8 + j1 * 8;

    #pragma unroll
    for (int k = 0; k < 8; k++) {
        float b1k = B[k];
        float v0 = A3_0[k] + B3_0[k];
        v0 = fmaf(A1i,  B2_0[k], v0);
        v0 = fmaf(A2p0, b1k,     v0);
        A3_0[k] = v0;
        float v1 = A3_1[k] + B3_1[k];
        v1 = fmaf(A1i,  B2_1[k], v1);
        v1 = fmaf(A2p1, b1k,     v1);
        A3_1[k] = v1;
    }
    A[8 + p0] = fmaf(A1i, B1j0, A2p0 + B[8 + p0]);
    A[8 + p1] = fmaf(A1i, B1j1, A2p1 + B[8 + p1]);
    __syncwarp();
    if (t < 8) A[t] += B[t];   // level-1 last (A1i already read by all lanes)
}

extern "C" __global__ void __launch_bounds__(256)
signature_kernel(const float* __restrict__ path, float* __restrict__ out) {
    __shared__ __align__(16) float sig[NCHUNK][SIGLEN];

    const int b = blockIdx.x;
    const int w = threadIdx.x >> 5;   // chunk id 0..7
    const int t = threadIdx.x & 31;   // lane

    const int p0 = 2 * t;
    const int p1 = p0 + 1;
    const int i  = p0 >> 3;           // i index shared by both owned pairs
    const int j0 = p0 & 7;            // even; j1 = j0+1 odd

    // loop-invariant select predicates for the SEL trees
    const bool i2 = (i & 4) != 0, i1 = (i & 2) != 0, i0 = (i & 1) != 0;
    const bool ja = (j0 & 4) != 0, jb = (j0 & 2) != 0;

    const float* base = path + ((size_t)b * L_STREAM + (size_t)w * CHUNK_STEPS) * CH;
    const int steps = (w < NCHUNK - 1) ? CHUNK_STEPS : (CHUNK_STEPS - 1); // 511 total

    // rows as 2x16B: row r = rows[2r], rows[2r+1]; base is 32B-aligned.
    const ulonglong2* __restrict__ rows = (const ulonglong2*)base;

    // previous-row channel values, packed as 4 f32x2 (all lanes identical)
    u64 prev01, prev23, prev45, prev67;
    {
        ulonglong2 ra = rows[0];
        ulonglong2 rb = rows[1];
        prev01 = ra.x; prev23 = ra.y; prev45 = rb.x; prev67 = rb.y;
    }
    const u64 first01 = prev01, first23 = prev23, first45 = prev45, first67 = prev67;

    float s1i = 0.f;                  // S1[i], the only S1 entry this lane needs
    float s2_0 = 0.f, s2_1 = 0.f;     // S2[p0], S2[p1]
    u64 s3[8];                        // S3[p0][0..7], S3[p1][0..7] packed as f32x2
    #pragma unroll
    for (int q = 0; q < 8; q++) s3[q] = 0ull;

    #pragma unroll 4
    for (int s = 0; s < steps; s++) {
        // whole next row, uniform address across the warp (L1 broadcast)
        ulonglong2 ra = rows[2 * (s + 1)];
        ulonglong2 rb = rows[2 * (s + 1) + 1];

        // dx = row - prev, packed
        u64 dxp0 = ffma2(prev01, NEG1X2, ra.x);
        u64 dxp1 = ffma2(prev23, NEG1X2, ra.y);
        u64 dxp2 = ffma2(prev45, NEG1X2, rb.x);
        u64 dxp3 = ffma2(prev67, NEG1X2, rb.y);
        prev01 = ra.x; prev23 = ra.y; prev45 = rb.x; prev67 = rb.y;

        // scalar views (register-pair aliases; movs are cheap/eliminated)
        float d0, d1, d2, d3, d4, d5, d6, d7;
        unpk2(dxp0, d0, d1);
        unpk2(dxp1, d2, d3);
        unpk2(dxp2, d4, d5);
        unpk2(dxp3, d6, d7);

        // di = d[i], dj0 = d[j0] (even), dj1 = d[j0+1] (odd): SEL trees on
        // loop-invariant predicates (ALU pipe).
        float di  = i2 ? (i1 ? (i0 ? d7 : d6) : (i0 ? d5 : d4))
                       : (i1 ? (i0 ? d3 : d2) : (i0 ? d1 : d0));
        float dj0 = ja ? (jb ? d6 : d4) : (jb ? d2 : d0);
        float dj1 = ja ? (jb ? d7 : d5) : (jb ? d3 : d1);

        // S3[p][k] += dx_k * ( dx_j*(dx_i/6 + S1_i/2) + S2_p )
        // S2[p]    += dx_j * ( dx_i/2 + S1_i )
        // (S1, S2 read as pre-step values)
        float g = fmaf(s1i, 0.5f, di * (1.0f / 6.0f));
        float h = fmaf(di, 0.5f, s1i);
        float a0 = fmaf(dj0, g, s2_0);
        float a1 = fmaf(dj1, g, s2_1);
        s2_0 = fmaf(dj0, h, s2_0);
        s2_1 = fmaf(dj1, h, s2_1);
        s1i += di;

        u64 a00 = pk2(a0, a0);
        u64 a11 = pk2(a1, a1);
        s3[0] = ffma2(dxp0, a00, s3[0]);
        s3[1] = ffma2(dxp1, a00, s3[1]);
        s3[2] = ffma2(dxp2, a00, s3[2]);
        s3[3] = ffma2(dxp3, a00, s3[3]);
        s3[4] = ffma2(dxp0, a11, s3[4]);
        s3[5] = ffma2(dxp1, a11, s3[5]);
        s3[6] = ffma2(dxp2, a11, s3[6]);
        s3[7] = ffma2(dxp3, a11, s3[7]);
    }

    // ---- publish chunk partial signature to shared ----
    // S1 = last row - first row (packed); lane 0 stores all 8 channels.
    if (t == 0) {
        u64* s1p = (u64*)sig[w];   // 16B-aligned base + 2336B row stride
        s1p[0] = ffma2(first01, NEG1X2, prev01);
        s1p[1] = ffma2(first23, NEG1X2, prev23);
        s1p[2] = ffma2(first45, NEG1X2, prev45);
        s1p[3] = ffma2(first67, NEG1X2, prev67);
    }
    sig[w][8 + p0] = s2_0;
    sig[w][8 + p1] = s2_1;
    #pragma unroll
    for (int q = 0; q < 4; q++) {
        float lo, hi;
        unpk2(s3[q], lo, hi);
        sig[w][72 + p0 * 8 + 2 * q]     = lo;
        sig[w][72 + p0 * 8 + 2 * q + 1] = hi;
        unpk2(s3[4 + q], lo, hi);
        sig[w][72 + p1 * 8 + 2 * q]     = lo;
        sig[w][72 + p1 * 8 + 2 * q + 1] = hi;
    }
    __syncthreads();

    // ---- 3-round Chen tree combine (order-preserving) ----
    if (w < 4) chen_combine_warp(sig[2 * w], sig[2 * w + 1], t);   // (0,1)(2,3)(4,5)(6,7)
    __syncthreads();
    if (w < 2) chen_combine_warp(sig[4 * w], sig[4 * w + 2], t);   // (0,2)(4,6)
    __syncthreads();
    if (w == 0) chen_combine_warp(sig[0], sig[4], t);              // (0,4)
    __syncthreads();

    float* o = out + (size_t)b * SIGLEN;
    for (int idx = threadIdx.x; idx < SIGLEN; idx += 256) o[idx] = sig[0][idx];
}

extern "C" void kernel_launch(void* const* d_in, const int* in_sizes, int n_in,
                              void* d_out, int out_size) {
    const float* path = (const float*)d_in[0];
    float* out = (float*)d_out;
    const int batches = in_sizes[0] / (L_STREAM * CH);   // 512
    signature_kernel<<<batches, 256>>>(path, out);
}

// round 11
// speedup vs baseline: 1.5838x; 1.1745x over previous
#include <cuda_runtime.h>
#include <cstddef>

// Truncated depth-3 path signature, B=512, L=512, C=8.
// out[b] = concat(S1(8), S2(64), S3(512)) = 584 floats per batch.
//
// Chen-associative chunked scan: 8 chunks per batch, one warp per
// (batch, chunk). R11: the whole batch (16KB) is staged into shared
// memory once with coalesced float4 loads; the hot loop reads each row
// with 2 uniform-address LDS.128 (broadcast, conflict-free). R10 profile
// showed issue=36.6% with occupancy capped: correlated stalls from the
// L1tex global-load queue (8 warps x front-batched LDG.128). LDS has a
// 2-cyc structural floor (vs 4 for LDG) and no global queue.
// dx = row - prev computed as packed f32x2 (fma.rn.f32x2).

#define FULLMASK 0xffffffffu
#define L_STREAM 512
#define CH 8
#define NCHUNK 8
#define CHUNK_STEPS 64          // chunks 0..6 have 64 increments, chunk 7 has 63
#define SIGLEN 584              // 8 + 64 + 512

typedef unsigned long long u64;

#define NEG1X2 0xBF800000BF800000ull   // packed {-1.0f, -1.0f}

__device__ __forceinline__ u64 pk2(float lo, float hi) {
    u64 r;
    asm("mov.b64 %0, {%1, %2};" : "=l"(r) : "f"(lo), "f"(hi));
    return r;
}
__device__ __forceinline__ void unpk2(u64 v, float& lo, float& hi) {
    asm("mov.b64 {%0, %1}, %2;" : "=f"(lo), "=f"(hi) : "l"(v));
}
// Packed fp32x2 FMA (Blackwell sm_100+): two FFMAs per instruction.
__device__ __forceinline__ u64 ffma2(u64 a, u64 b, u64 c) {
    u64 d;
    asm("fma.rn.f32x2 %0, %1, %2, %3;" : "=l"(d) : "l"(a), "l"(b), "l"(c));
    return d;
}

// Warp-collective Chen combine: A <- A o B, both in shared memory.
// Lane t owns flat S2/S3 pairs p0=2t, p1=2t+1 (both share i = p0>>3).
__device__ __forceinline__ void chen_combine_warp(float* A, const float* B, int t) {
    const int p0 = 2 * t, p1 = p0 + 1;
    const int i = p0 >> 3, j0 = p0 & 7, j1 = j0 + 1;

    const float A1i  = A[i];
    const float B1j0 = B[j0];
    const float B1j1 = B[j1];
    const float A2p0 = A[8 + p0];
    const float A2p1 = A[8 + p1];

    float*       A3_0 = A + 72 + p0 * 8;
    float*       A3_1 = A + 72 + p1 * 8;
    const float* B3_0 = B + 72 + p0 * 8;
    const float* B3_1 = B + 72 + p1 * 8;
    const float* B2_0 = B + 8 + j0 * 8;
    const float* B2_1 = B + 8 + j1 * 8;

    #pragma unroll
    for (int k = 0; k < 8; k++) {
        float b1k = B[k];
        float v0 = A3_0[k] + B3_0[k];
        v0 = fmaf(A1i,  B2_0[k], v0);
        v0 = fmaf(A2p0, b1k,     v0);
        A3_0[k] = v0;
        float v1 = A3_1[k] + B3_1[k];
        v1 = fmaf(A1i,  B2_1[k], v1);
        v1 = fmaf(A2p1, b1k,     v1);
        A3_1[k] = v1;
    }
    A[8 + p0] = fmaf(A1i, B1j0, A2p0 + B[8 + p0]);
    A[8 + p1] = fmaf(A1i, B1j1, A2p1 + B[8 + p1]);
    __syncwarp();
    if (t < 8) A[t] += B[t];   // level-1 last (A1i already read by all lanes)
}

extern "C" __global__ void __launch_bounds__(256)
signature_kernel(const float* __restrict__ path, float* __restrict__ out) {
    __shared__ __align__(16) float buf[L_STREAM * CH];   // 16KB: whole batch path
    __shared__ __align__(16) float sig[NCHUNK][SIGLEN];  // 18.7KB: chunk partials

    const int b = blockIdx.x;
    const int w = threadIdx.x >> 5;   // chunk id 0..7
    const int t = threadIdx.x & 31;   // lane

    // ---- stage the whole batch into shared (coalesced float4) ----
    {
        const float4* __restrict__ g4 = (const float4*)(path + (size_t)b * L_STREAM * CH);
        float4* s4 = (float4*)buf;
        #pragma unroll
        for (int k = 0; k < 4; k++)
            s4[threadIdx.x + 256 * k] = g4[threadIdx.x + 256 * k];
    }
    __syncthreads();

    const int p0 = 2 * t;
    const int p1 = p0 + 1;
    const int i  = p0 >> 3;           // i index shared by both owned pairs
    const int j0 = p0 & 7;            // even; j1 = j0+1 odd

    // loop-invariant select predicates for the SEL trees
    const bool i2 = (i & 4) != 0, i1 = (i & 2) != 0, i0 = (i & 1) != 0;
    const bool ja = (j0 & 4) != 0, jb = (j0 & 2) != 0;

    const int steps = (w < NCHUNK - 1) ? CHUNK_STEPS : (CHUNK_STEPS - 1); // 511 total

    // chunk rows in shared: row r = rows[2r], rows[2r+1] (16B each)
    const ulonglong2* __restrict__ rows =
        (const ulonglong2*)(buf + w * CHUNK_STEPS * CH);

    // previous-row channel values, packed as 4 f32x2 (all lanes identical)
    u64 prev01, prev23, prev45, prev67;
    {
        ulonglong2 ra = rows[0];
        ulonglong2 rb = rows[1];
        prev01 = ra.x; prev23 = ra.y; prev45 = rb.x; prev67 = rb.y;
    }

    float s1i = 0.f;                  // S1[i], the only S1 entry this lane needs
    float s2_0 = 0.f, s2_1 = 0.f;     // S2[p0], S2[p1]
    u64 s3[8];                        // S3[p0][0..7], S3[p1][0..7] packed as f32x2
    #pragma unroll
    for (int q = 0; q < 8; q++) s3[q] = 0ull;

    #pragma unroll 4
    for (int s = 0; s < steps; s++) {
        // next row from shared, uniform address across the warp (broadcast)
        ulonglong2 ra = rows[2 * (s + 1)];
        ulonglong2 rb = rows[2 * (s + 1) + 1];

        // dx = row - prev, packed
        u64 dxp0 = ffma2(prev01, NEG1X2, ra.x);
        u64 dxp1 = ffma2(prev23, NEG1X2, ra.y);
        u64 dxp2 = ffma2(prev45, NEG1X2, rb.x);
        u64 dxp3 = ffma2(prev67, NEG1X2, rb.y);
        prev01 = ra.x; prev23 = ra.y; prev45 = rb.x; prev67 = rb.y;

        // scalar views (register-pair aliases; movs are cheap/eliminated)
        float d0, d1, d2, d3, d4, d5, d6, d7;
        unpk2(dxp0, d0, d1);
        unpk2(dxp1, d2, d3);
        unpk2(dxp2, d4, d5);
        unpk2(dxp3, d6, d7);

        // di = d[i], dj0 = d[j0] (even), dj1 = d[j0+1] (odd): SEL trees on
        // loop-invariant predicates (ALU pipe).
        float di  = i2 ? (i1 ? (i0 ? d7 : d6) : (i0 ? d5 : d4))
                       : (i1 ? (i0 ? d3 : d2) : (i0 ? d1 : d0));
        float dj0 = ja ? (jb ? d6 : d4) : (jb ? d2 : d0);
        float dj1 = ja ? (jb ? d7 : d5) : (jb ? d3 : d1);

        // S3[p][k] += dx_k * ( dx_j*(dx_i/6 + S1_i/2) + S2_p )
        // S2[p]    += dx_j * ( dx_i/2 + S1_i )
        // (S1, S2 read as pre-step values)
        float g = fmaf(s1i, 0.5f, di * (1.0f / 6.0f));
        float h = fmaf(di, 0.5f, s1i);
        float a0 = fmaf(dj0, g, s2_0);
        float a1 = fmaf(dj1, g, s2_1);
        s2_0 = fmaf(dj0, h, s2_0);
        s2_1 = fmaf(dj1, h, s2_1);
        s1i += di;

        u64 a00 = pk2(a0, a0);
        u64 a11 = pk2(a1, a1);
        s3[0] = ffma2(dxp0, a00, s3[0]);
        s3[1] = ffma2(dxp1, a00, s3[1]);
        s3[2] = ffma2(dxp2, a00, s3[2]);
        s3[3] = ffma2(dxp3, a00, s3[3]);
        s3[4] = ffma2(dxp0, a11, s3[4]);
        s3[5] = ffma2(dxp1, a11, s3[5]);
        s3[6] = ffma2(dxp2, a11, s3[6]);
        s3[7] = ffma2(dxp3, a11, s3[7]);
    }

    // ---- publish chunk partial signature to shared ----
    // S1 = last row - first row; first row re-read from smem (saves regs).
    if (t == 0) {
        ulonglong2 fa = rows[0];
        ulonglong2 fb = rows[1];
        u64* s1p = (u64*)sig[w];   // 16B-aligned base + 2336B row stride
        s1p[0] = ffma2(fa.x, NEG1X2, prev01);
        s1p[1] = ffma2(fa.y, NEG1X2, prev23);
        s1p[2] = ffma2(fb.x, NEG1X2, prev45);
        s1p[3] = ffma2(fb.y, NEG1X2, prev67);
    }
    sig[w][8 + p0] = s2_0;
    sig[w][8 + p1] = s2_1;
    #pragma unroll
    for (int q = 0; q < 4; q++) {
        float lo, hi;
        unpk2(s3[q], lo, hi);
        sig[w][72 + p0 * 8 + 2 * q]     = lo;
        sig[w][72 + p0 * 8 + 2 * q + 1] = hi;
        unpk2(s3[4 + q], lo, hi);
        sig[w][72 + p1 * 8 + 2 * q]     = lo;
        sig[w][72 + p1 * 8 + 2 * q + 1] = hi;
    }
    __syncthreads();

    // ---- 3-round Chen tree combine (order-preserving) ----
    if (w < 4) chen_combine_warp(sig[2 * w], sig[2 * w + 1], t);   // (0,1)(2,3)(4,5)(6,7)
    __syncthreads();
    if (w < 2) chen_combine_warp(sig[4 * w], sig[4 * w + 2], t);   // (0,2)(4,6)
    __syncthreads();
    if (w == 0) chen_combine_warp(sig[0], sig[4], t);              // (0,4)
    __syncthreads();

    float* o = out + (size_t)b * SIGLEN;
    for (int idx = threadIdx.x; idx < SIGLEN; idx += 256) o[idx] = sig[0][idx];
}

extern "C" void kernel_launch(void* const* d_in, const int* in_sizes, int n_in,
                              void* d_out, int out_size) {
    const float* path = (const float*)d_in[0];
    float* out = (float*)d_out;
    const int batches = in_sizes[0] / (L_STREAM * CH);   // 512
    signature_kernel<<<batches, 256>>>(path, out);
}

// round 16
// speedup vs baseline: 1.9185x; 1.2113x over previous
#include <cuda_runtime.h>
#include <cstddef>

// Truncated depth-3 path signature, B=512, L=512, C=8.
// out[b] = concat(S1(8), S2(64), S3(512)) = 584 floats per batch.
//
// Chen-associative chunked scan: 8 chunks per batch, one warp per
// (batch, chunk). R12: increments dx are precomputed into shared during
// the staging pass (removes the dx ffma2s + prev chain from the hot
// loop); di and (dj0,dj1) are read directly with conflict-free scalar
// LDS (removes the 7-SEL trees); S2/a updates are packed f32x2 using
// the LDS.64 (dj0,dj1) pair as the packed operand. ~25 instrs/step.

#define FULLMASK 0xffffffffu
#define L_STREAM 512
#define CH 8
#define NCHUNK 8
#define CHUNK_STEPS 64          // chunks 0..6 have 64 increments, chunk 7 has 63
#define SIGLEN 584              // 8 + 64 + 512
#define NROWS4 1024             // float4 count of one batch (512 rows * 2)

typedef unsigned long long u64;

#define NEG1X2 0xBF800000BF800000ull   // packed {-1.0f, -1.0f}

__device__ __forceinline__ u64 pk2(float lo, float hi) {
    u64 r;
    asm("mov.b64 %0, {%1, %2};" : "=l"(r) : "f"(lo), "f"(hi));
    return r;
}
__device__ __forceinline__ void unpk2(u64 v, float& lo, float& hi) {
    asm("mov.b64 {%0, %1}, %2;" : "=f"(lo), "=f"(hi) : "l"(v));
}
// Packed fp32x2 FMA (Blackwell sm_100+): two FFMAs per instruction.
__device__ __forceinline__ u64 ffma2(u64 a, u64 b, u64 c) {
    u64 d;
    asm("fma.rn.f32x2 %0, %1, %2, %3;" : "=l"(d) : "l"(a), "l"(b), "l"(c));
    return d;
}

// Warp-collective Chen combine: A <- A o B, both in shared memory.
// Lane t owns flat S2/S3 pairs p0=2t, p1=2t+1 (both share i = p0>>3).
__device__ __forceinline__ void chen_combine_warp(float* A, const float* B, int t) {
    const int p0 = 2 * t, p1 = p0 + 1;
    const int i = p0 >> 3, j0 = p0 & 7, j1 = j0 + 1;

    const float A1i  = A[i];
    const float B1j0 = B[j0];
    const float B1j1 = B[j1];
    const float A2p0 = A[8 + p0];
    const float A2p1 = A[8 + p1];

    float*       A3_0 = A + 72 + p0 * 8;
    float*       A3_1 = A + 72 + p1 * 8;
    const float* B3_0 = B + 72 + p0 * 8;
    const float* B3_1 = B + 72 + p1 * 8;
    const float* B2_0 = B + 8 + j0 * 8;
    const float* B2_1 = B + 8 + j1 * 8;

    #pragma unroll
    for (int k = 0; k < 8; k++) {
        float b1k = B[k];
        float v0 = A3_0[k] + B3_0[k];
        v0 = fmaf(A1i,  B2_0[k], v0);
        v0 = fmaf(A2p0, b1k,     v0);
        A3_0[k] = v0;
        float v1 = A3_1[k] + B3_1[k];
        v1 = fmaf(A1i,  B2_1[k], v1);
        v1 = fmaf(A2p1, b1k,     v1);
        A3_1[k] = v1;
    }
    A[8 + p0] = fmaf(A1i, B1j0, A2p0 + B[8 + p0]);
    A[8 + p1] = fmaf(A1i, B1j1, A2p1 + B[8 + p1]);
    __syncwarp();
    if (t < 8) A[t] += B[t];   // level-1 last (A1i already read by all lanes)
}

extern "C" __global__ void __launch_bounds__(256)
signature_kernel(const float* __restrict__ path, float* __restrict__ out) {
    __shared__ __align__(16) float dxbuf[L_STREAM * CH];  // 16KB: dx rows 0..510
    __shared__ __align__(16) float sig[NCHUNK][SIGLEN];   // 18.7KB: chunk partials

    const int b = blockIdx.x;
    const int w = threadIdx.x >> 5;   // chunk id 0..7
    const int t = threadIdx.x & 31;   // lane

    // ---- stage increments: dx4[i] = p4[i+2] - p4[i] (coalesced) ----
    {
        const ulonglong2* __restrict__ g2 =
            (const ulonglong2*)(path + (size_t)b * L_STREAM * CH);
        ulonglong2* s2 = (ulonglong2*)dxbuf;
        #pragma unroll
        for (int k = 0; k < 4; k++) {
            int idx = threadIdx.x + 256 * k;       // float4 index 0..1023
            if (idx < NROWS4 - 2) {                // dx rows 0..510
                ulonglong2 a = g2[idx];
                ulonglong2 c = g2[idx + 2];        // next row, same half
                ulonglong2 d;
                d.x = ffma2(a.x, NEG1X2, c.x);
                d.y = ffma2(a.y, NEG1X2, c.y);
                s2[idx] = d;
            }
        }
    }
    __syncthreads();

    const int p0 = 2 * t;
    const int p1 = p0 + 1;
    const int i  = p0 >> 3;           // i index shared by both owned pairs
    const int jh = t & 3;             // (j0>>1): 64-bit index of the (dj0,dj1) pair

    const int steps = (w < NCHUNK - 1) ? CHUNK_STEPS : (CHUNK_STEPS - 1); // 511 total

    // this warp's dx rows in shared
    const float*      dxf = dxbuf + w * CHUNK_STEPS * CH;
    const u64*        dxd = (const u64*)dxf;
    const ulonglong2* dxr = (const ulonglong2*)dxf;

    float s1i = 0.f;                  // S1[i], the only S1 entry this lane needs
    u64 s2p = 0ull;                   // packed {S2[p0], S2[p1]}
    u64 s3[8];                        // S3[p0][0..7], S3[p1][0..7] packed as f32x2
    #pragma unroll
    for (int q = 0; q < 8; q++) s3[q] = 0ull;

    #pragma unroll 4
    for (int s = 0; s < steps; s++) {
        // dx row (uniform broadcast) + this lane's scalars (conflict-free)
        ulonglong2 da = dxr[2 * s];        // {d0,d1},{d2,d3}
        ulonglong2 db = dxr[2 * s + 1];    // {d4,d5},{d6,d7}
        float di  = dxf[s * 8 + i];
        u64   djp = dxd[s * 4 + jh];       // packed {dj0, dj1}

        // S3[p][k] += dx_k * ( dx_j*(dx_i/6 + S1_i/2) + S2_p )
        // S2[p]    += dx_j * ( dx_i/2 + S1_i )      (pre-step S1, S2)
        float g = fmaf(s1i, 0.5f, di * (1.0f / 6.0f));
        float h = fmaf(di, 0.5f, s1i);
        u64 gg = pk2(g, g);
        u64 hh = pk2(h, h);
        u64 a01 = ffma2(djp, gg, s2p);     // {a0, a1}
        s2p = ffma2(djp, hh, s2p);
        s1i += di;

        float a0, a1;
        unpk2(a01, a0, a1);
        u64 a00 = pk2(a0, a0);
        u64 a11 = pk2(a1, a1);
        s3[0] = ffma2(da.x, a00, s3[0]);
        s3[1] = ffma2(da.y, a00, s3[1]);
        s3[2] = ffma2(db.x, a00, s3[2]);
        s3[3] = ffma2(db.y, a00, s3[3]);
        s3[4] = ffma2(da.x, a11, s3[4]);
        s3[5] = ffma2(da.y, a11, s3[5]);
        s3[6] = ffma2(db.x, a11, s3[6]);
        s3[7] = ffma2(db.y, a11, s3[7]);
    }

    // ---- publish chunk partial signature to shared ----
    // S1 = last row - first row of this chunk, read from global (once).
    if (t == 0) {
        const ulonglong2* gp2 = (const ulonglong2*)
            (path + ((size_t)b * L_STREAM + (size_t)w * CHUNK_STEPS) * CH);
        ulonglong2 f0 = gp2[0];
        ulonglong2 f1 = gp2[1];
        ulonglong2 l0 = gp2[2 * steps];
        ulonglong2 l1 = gp2[2 * steps + 1];
        u64* s1p = (u64*)sig[w];   // 16B-aligned base + 2336B row stride
        s1p[0] = ffma2(f0.x, NEG1X2, l0.x);
        s1p[1] = ffma2(f0.y, NEG1X2, l0.y);
        s1p[2] = ffma2(f1.x, NEG1X2, l1.x);
        s1p[3] = ffma2(f1.y, NEG1X2, l1.y);
    }
    {
        float s2_0, s2_1;
        unpk2(s2p, s2_0, s2_1);
        sig[w][8 + p0] = s2_0;
        sig[w][8 + p1] = s2_1;
    }
    #pragma unroll
    for (int q = 0; q < 4; q++) {
        float lo, hi;
        unpk2(s3[q], lo, hi);
        sig[w][72 + p0 * 8 + 2 * q]     = lo;
        sig[w][72 + p0 * 8 + 2 * q + 1] = hi;
        unpk2(s3[4 + q], lo, hi);
        sig[w][72 + p1 * 8 + 2 * q]     = lo;
        sig[w][72 + p1 * 8 + 2 * q + 1] = hi;
    }
    __syncthreads();

    // ---- 3-round Chen tree combine (order-preserving) ----
    if (w < 4) chen_combine_warp(sig[2 * w], sig[2 * w + 1], t);   // (0,1)(2,3)(4,5)(6,7)
    __syncthreads();
    if (w < 2) chen_combine_warp(sig[4 * w], sig[4 * w + 2], t);   // (0,2)(4,6)
    __syncthreads();
    if (w == 0) chen_combine_warp(sig[0], sig[4], t);              // (0,4)
    __syncthreads();

    float* o = out + (size_t)b * SIGLEN;
    for (int idx = threadIdx.x; idx < SIGLEN; idx += 256) o[idx] = sig[0][idx];
}

extern "C" void kernel_launch(void* const* d_in, const int* in_sizes, int n_in,
                              void* d_out, int out_size) {
    const float* path = (const float*)d_in[0];
    float* out = (float*)d_out;
    const int batches = in_sizes[0] / (L_STREAM * CH);   // 512
    signature_kernel<<<batches, 256>>>(path, out);
}